// round 14
// baseline (speedup 1.0000x reference)
#include <cuda_runtime.h>
#include <cuda_bf16.h>
#include <cuda_fp16.h>
#include <math.h>

typedef unsigned long long ull;

#define PNUM 2548      // number of masked positions (exact)
#define PPAD 2560      // padded N for GEMM
#define QMAX 16384
#define CIN  768
#define MROWS 6912     // 9 offsets * 768 cout, ordered m = o*768 + c
#define KK   2304      // 3 * 768 (hh bf16 | a_hi*b_lo fp16 | a_lo*b_hi fp16)
#define NCH  72        // K chunks of 32
#define NCH_HH 24      // chunks in segment 0 (fp32 accum)

// ---------------- scratch (static device globals; no allocation) -------------
__device__ float d_V[CIN * PPAD];
__device__ __align__(128) __nv_bfloat16 d_A2[(size_t)MROWS * KK]; // weights [m][k]
__device__ __align__(128) __nv_bfloat16 d_B2[(size_t)PPAD * KK];  // values  [p][k]
__device__ float d_Yt[(size_t)PPAD * MROWS];   // GEMM out, [p][m]
__device__ float d_H[(size_t)QMAX * CIN];      // conv1 out, masked q rows only
__device__ float d_gps[QMAX * 4];              // per-q group sums
__device__ float d_gpq[QMAX * 4];              // per-q group sumsq
__device__ int   d_pidx[QMAX];
__device__ unsigned char d_flags[QMAX];
__device__ int   d_bcnt[128];
__device__ int   d_boff[128];
__device__ int   d_src[QMAX * 12];
__device__ int   d_q2p[QMAX];
__device__ int   d_qofp[PNUM];
__device__ int   d_qcount;
__device__ int   d_ppi[PNUM];
__device__ int   d_ppj[PNUM];
__device__ float d_mu[4];
__device__ float d_rs[4];
__device__ float d_scores[PNUM];

// ---------------- helpers ------------------------------------------------------
__device__ __forceinline__ unsigned smem_u32(const void* p) {
    unsigned a;
    asm("{ .reg .u64 t; cvta.to.shared.u64 t, %1; cvt.u32.u64 %0, t; }" : "=r"(a) : "l"(p));
    return a;
}
__device__ __forceinline__ void cp16(unsigned dst, const void* src) {
    asm volatile("cp.async.cg.shared.global [%0], [%1], 16;" :: "r"(dst), "l"(src) : "memory");
}
__device__ __forceinline__ void cp_commit() {
    asm volatile("cp.async.commit_group;" ::: "memory");
}
__device__ __forceinline__ void cp_wait1() {
    asm volatile("cp.async.wait_group 1;" ::: "memory");
}
__device__ __forceinline__ void cp_wait0() {
    asm volatile("cp.async.wait_group 0;" ::: "memory");
}
__device__ __forceinline__ void ldmx4(unsigned addr, unsigned& r0, unsigned& r1, unsigned& r2, unsigned& r3) {
    asm volatile("ldmatrix.sync.aligned.m8n8.x4.shared.b16 {%0,%1,%2,%3}, [%4];"
                 : "=r"(r0), "=r"(r1), "=r"(r2), "=r"(r3) : "r"(addr));
}
__device__ __forceinline__ void mma16816(float* c, const unsigned* a, const unsigned* b) {
    asm volatile(
        "mma.sync.aligned.m16n8k16.row.col.f32.bf16.bf16.f32 "
        "{%0,%1,%2,%3},{%4,%5,%6,%7},{%8,%9},{%0,%1,%2,%3};"
        : "+f"(c[0]), "+f"(c[1]), "+f"(c[2]), "+f"(c[3])
        : "r"(a[0]), "r"(a[1]), "r"(a[2]), "r"(a[3]), "r"(b[0]), "r"(b[1]));
}
// fp16-accumulate HMMA: D,C are 2x .f16x2 regs
__device__ __forceinline__ void mma16816h(unsigned* c, const unsigned* a, const unsigned* b) {
    asm volatile(
        "mma.sync.aligned.m16n8k16.row.col.f16.f16.f16.f16 "
        "{%0,%1},{%2,%3,%4,%5},{%6,%7},{%0,%1};"
        : "+r"(c[0]), "+r"(c[1])
        : "r"(a[0]), "r"(a[1]), "r"(a[2]), "r"(a[3]), "r"(b[0]), "r"(b[1]));
}
__device__ __forceinline__ unsigned pkbf2(float a, float b) {
    __nv_bfloat16 x = __float2bfloat16_rn(a), y = __float2bfloat16_rn(b);
    unsigned short ux = *(unsigned short*)&x, uy = *(unsigned short*)&y;
    return (unsigned)ux | ((unsigned)uy << 16);
}
__device__ __forceinline__ unsigned pkhf2(float a, float b) {
    __half2 h = __floats2half2_rn(a, b);
    return *(unsigned*)&h;
}
__device__ __forceinline__ float2 h2f(unsigned u) {
    __half2 h = *(__half2*)&u;
    return __half22float2(h);
}

// ---------------- K0: table fill (block 0) + max pool (blocks 1..96) ------------
__global__ void __launch_bounds__(1024) k_init(const float* __restrict__ fea) {
    __shared__ float xs[8][128];
    const int tid = threadIdx.x;

    if (blockIdx.x == 0) {
        for (int i = tid; i < QMAX; i += 1024) d_pidx[i] = -1;
        __syncthreads();
        if (tid < 128) { d_ppi[tid] = tid; d_ppj[tid] = tid; d_pidx[tid * 128 + tid] = tid; }
        int len = 128, pbase = 128, stride = 1, offset = 0;
        const int counts[4] = {15, 8, 8, 8};
        for (int g = 0; g < 4; ++g) {
            for (int t = 0; t < counts[g]; ++t) {
                offset += stride;
                bool k3 = (g > 0 && t == 0);
                int nl = k3 ? (len - 1) / 2 : (len - 1);
                for (int u = tid; u < nl; u += 1024) {
                    int ii = u * stride, jj = offset + u * stride, p = pbase + u;
                    d_ppi[p] = ii; d_ppj[p] = jj; d_pidx[ii * 128 + jj] = p;
                }
                pbase += nl; len = nl;
            }
            stride <<= 1;
        }
    } else {
        const int sub = tid >> 7;
        const int lt = tid & 127;
        const int c = (blockIdx.x - 1) * 8 + sub;
        float* x = xs[sub];
        x[lt] = fea[c * 128 + lt];
        d_V[c * PPAD + lt] = x[lt];
        __syncthreads();
        int len = 128, pbase = 128, stride = 1, offset = 0;
        const int counts[4] = {15, 8, 8, 8};
        for (int g = 0; g < 4; ++g) {
            for (int t = 0; t < counts[g]; ++t) {
                offset += stride;
                bool k3 = (g > 0 && t == 0);
                int nl = k3 ? (len - 1) / 2 : (len - 1);
                float v = 0.f;
                if (lt < nl)
                    v = k3 ? fmaxf(fmaxf(x[2 * lt], x[2 * lt + 1]), x[2 * lt + 2])
                           : fmaxf(x[lt], x[lt + 1]);
                __syncthreads();
                if (lt < nl) { x[lt] = v; d_V[c * PPAD + pbase + lt] = v; }
                __syncthreads();
                pbase += nl; len = nl;
            }
            stride <<= 1;
        }
    }
}

// ---------------- K1: dilation flags + per-block counts --------------------------
__global__ void __launch_bounds__(128) k_flag() {
    const int cell = blockIdx.x * 128 + threadIdx.x;
    const int qi = cell >> 7, qj = cell & 127;
    bool f = false;
    #pragma unroll
    for (int o = 0; o < 9; ++o) {
        int ni = qi + o / 3 - 1, nj = qj + o % 3 - 1;
        if (ni >= 0 && ni < 128 && nj >= 0 && nj < 128 && d_pidx[ni * 128 + nj] >= 0) f = true;
    }
    d_flags[cell] = f ? 1 : 0;
    unsigned b = __ballot_sync(0xffffffff, f);
    __shared__ int wc[4];
    if ((threadIdx.x & 31) == 0) wc[threadIdx.x >> 5] = __popc(b);
    __syncthreads();
    if (threadIdx.x == 0) d_bcnt[blockIdx.x] = wc[0] + wc[1] + wc[2] + wc[3];
}

// ---------------- K2: merged A' + B' build (mixed bf16/fp16 segments) ------------
__global__ void __launch_bounds__(256) k_split(const float* __restrict__ w) {
    const int tid = threadIdx.x;
    if (blockIdx.x < 768) {
        const int cout = blockIdx.x;
        __shared__ float ws[CIN * 9];
        for (int i = tid; i < CIN * 9; i += 256) ws[i] = w[(size_t)cout * CIN * 9 + i];
        __syncthreads();
        #pragma unroll
        for (int o = 0; o < 9; ++o) {
            size_t mrow = (size_t)(o * 768 + cout) * KK;
            for (int k2 = tid; k2 < 384; k2 += 256) {
                int k = k2 * 2;
                float x0 = ws[k * 9 + o], x1 = ws[(k + 1) * 9 + o];
                float h0f = __bfloat162float(__float2bfloat16_rn(x0));
                float h1f = __bfloat162float(__float2bfloat16_rn(x1));
                *(unsigned*)&d_A2[mrow + k]        = pkbf2(x0, x1);            // hh (bf16)
                *(unsigned*)&d_A2[mrow + 768 + k]  = pkhf2(h0f, h1f);          // a_hi (fp16)
                *(unsigned*)&d_A2[mrow + 1536 + k] = pkhf2(x0 - h0f, x1 - h1f);// a_lo (fp16)
            }
        }
    } else {
        __shared__ float tile[32][33];
        const int b = blockIdx.x - 768;        // 0..1919
        const int p0 = (b % 80) * 32;
        const int c0 = (b / 80) * 32;
        const int tx = tid & 31, ty = tid >> 5; // (32,8)
        #pragma unroll
        for (int i = ty; i < 32; i += 8)
            tile[i][tx] = (p0 + tx < PNUM) ? d_V[(size_t)(c0 + i) * PPAD + p0 + tx] : 0.f;
        __syncthreads();
        #pragma unroll
        for (int i = ty; i < 32; i += 8) {
            if (tx < 16) {
                int p = p0 + i;
                int k = c0 + tx * 2;
                float x0 = tile[tx * 2][i], x1 = tile[tx * 2 + 1][i];
                float h0f = __bfloat162float(__float2bfloat16_rn(x0));
                float h1f = __bfloat162float(__float2bfloat16_rn(x1));
                size_t prow = (size_t)p * KK;
                *(unsigned*)&d_B2[prow + k]        = pkbf2(x0, x1);            // hh (bf16)
                *(unsigned*)&d_B2[prow + 768 + k]  = pkhf2(x0 - h0f, x1 - h1f);// b_lo (fp16)
                *(unsigned*)&d_B2[prow + 1536 + k] = pkhf2(h0f, h1f);          // b_hi (fp16)
            }
        }
    }
}

// ---------------- K3: mixed-precision mma.sync GEMM  Yt = B2 @ A2^T -------------
// CTA 128x128, 8 warps (2m x 4n), warp 64x32. Segment 0 (24 chunks): bf16/f32 acc.
// Segments 1-2 (48 chunks): fp16/f16 acc into separate fragment; summed in epilogue.
__global__ void __launch_bounds__(256, 1) k_gemm_mma() {
    __shared__ __align__(16) uint4 smbuf[3][1024];   // per stage: A 8KB | B 8KB
    const int tid = threadIdx.x;
    const int wid = tid >> 5;
    const int lane = tid & 31;
    const int wm = wid >> 2;            // 0..1 (p rows)
    const int wn = wid & 3;             // 0..3 (m cols)
    const int bn0 = blockIdx.x * 128;   // over MROWS
    const int bm0 = blockIdx.y * 128;   // over PPAD

    const unsigned smb = smem_u32(&smbuf[0][0]);

    const __nv_bfloat16* Ag = d_B2 + (size_t)bm0 * KK;   // M-side: values (p rows)
    const __nv_bfloat16* Bg = d_A2 + (size_t)bn0 * KK;   // N-side: weights (m rows)

    auto issue = [&](int kc, int buf) {
        unsigned base = smb + buf * 16384;
        #pragma unroll
        for (int j = 0; j < 4; ++j) {
            int cid = tid + j * 256;
            int half = cid >> 9;
            int lc = cid & 511;
            int r = lc >> 2, c = lc & 3;
            unsigned dst = base + half * 8192 + (unsigned)(r * 64 + ((c ^ ((r >> 1) & 3)) << 4));
            const __nv_bfloat16* src = (half ? Bg : Ag) + (size_t)r * KK + kc * 32 + c * 8;
            cp16(dst, src);
        }
        cp_commit();
    };

    float acc[4][4][4];
    unsigned hacc[4][4][2];
    #pragma unroll
    for (int i = 0; i < 4; i++)
        #pragma unroll
        for (int j = 0; j < 4; j++) {
            #pragma unroll
            for (int v = 0; v < 4; v++) acc[i][j][v] = 0.f;
            hacc[i][j][0] = 0u; hacc[i][j][1] = 0u;
        }

    issue(0, 0);
    issue(1, 1);

    const int l15 = lane & 15, hl = lane >> 4;
    const int rowA = wm * 64 + l15;
    const int sA = (rowA >> 1) & 3;
    const int rowB0 = wn * 32 + l15;
    const int rowB1 = rowB0 + 16;
    const int sB0 = (rowB0 >> 1) & 3;
    const int sB1 = (rowB1 >> 1) & 3;

    for (int kt = 0; kt < NCH; ++kt) {
        if (kt < NCH - 1) cp_wait1(); else cp_wait0();
        __syncthreads();
        if (kt + 2 < NCH) issue(kt + 2, (kt + 2) % 3);

        unsigned Asm = smb + (kt % 3) * 16384;
        unsigned Bsm = Asm + 8192;
        const bool hh = (kt < NCH_HH);

        #pragma unroll
        for (int kg = 0; kg < 2; ++kg) {
            unsigned af[4][4], bf[4][2];
            #pragma unroll
            for (int mt = 0; mt < 4; ++mt) {
                unsigned addr = Asm + (unsigned)((rowA + mt * 16) * 64 + (((kg * 2 + hl) ^ sA) << 4));
                ldmx4(addr, af[mt][0], af[mt][1], af[mt][2], af[mt][3]);
            }
            {
                unsigned addr0 = Bsm + (unsigned)(rowB0 * 64 + (((kg * 2 + hl) ^ sB0) << 4));
                unsigned r0, r1, r2, r3;
                ldmx4(addr0, r0, r1, r2, r3);
                bf[0][0] = r0; bf[1][0] = r1; bf[0][1] = r2; bf[1][1] = r3;
                unsigned addr1 = Bsm + (unsigned)(rowB1 * 64 + (((kg * 2 + hl) ^ sB1) << 4));
                ldmx4(addr1, r0, r1, r2, r3);
                bf[2][0] = r0; bf[3][0] = r1; bf[2][1] = r2; bf[3][1] = r3;
            }
            if (hh) {
                #pragma unroll
                for (int mt = 0; mt < 4; ++mt)
                    #pragma unroll
                    for (int nt = 0; nt < 4; ++nt)
                        mma16816(acc[mt][nt], af[mt], bf[nt]);
            } else {
                #pragma unroll
                for (int mt = 0; mt < 4; ++mt)
                    #pragma unroll
                    for (int nt = 0; nt < 4; ++nt)
                        mma16816h(hacc[mt][nt], af[mt], bf[nt]);
            }
        }
        __syncthreads();
    }

    const int r0 = lane >> 2, c0 = (lane & 3) * 2;
    #pragma unroll
    for (int mt = 0; mt < 4; ++mt) {
        int m = bm0 + wm * 64 + mt * 16 + r0;   // p row
        float* y0 = d_Yt + (size_t)m * MROWS + bn0 + wn * 32;
        float* y1 = y0 + (size_t)8 * MROWS;
        #pragma unroll
        for (int nt = 0; nt < 4; ++nt) {
            float2 cl = h2f(hacc[mt][nt][0]);
            float2 ch = h2f(hacc[mt][nt][1]);
            *(float2*)(y0 + nt * 8 + c0) = make_float2(acc[mt][nt][0] + cl.x,
                                                       acc[mt][nt][1] + cl.y);
            *(float2*)(y1 + nt * 8 + c0) = make_float2(acc[mt][nt][2] + ch.x,
                                                       acc[mt][nt][3] + ch.y);
        }
    }
}

// ---------------- K4: block-offset prefix scan -----------------------------------
__global__ void __launch_bounds__(128) k_offs() {
    const int tid = threadIdx.x;
    __shared__ int s[128];
    s[tid] = d_bcnt[tid];
    __syncthreads();
    int v = s[tid];
    for (int off = 1; off < 128; off <<= 1) {
        int u = (tid >= off) ? s[tid - off] : 0;
        __syncthreads();
        s[tid] += u;
        __syncthreads();
    }
    d_boff[tid] = s[tid] - v;   // exclusive
    if (tid == 127) d_qcount = s[127];
}

// ---------------- K5: emit q tables (parallel) ------------------------------------
__global__ void __launch_bounds__(128) k_emit() {
    const int tid = threadIdx.x;
    const int cell = blockIdx.x * 128 + tid;
    const int lane = tid & 31, warp = tid >> 5;
    bool f = d_flags[cell] != 0;
    unsigned b = __ballot_sync(0xffffffff, f);
    __shared__ int wbase[4];
    if (lane == 0) wbase[warp] = __popc(b);
    __syncthreads();
    if (tid == 0) {
        int acc = d_boff[blockIdx.x];
        #pragma unroll
        for (int wdx = 0; wdx < 4; ++wdx) { int t = wbase[wdx]; wbase[wdx] = acc; acc += t; }
    }
    __syncthreads();
    if (f) {
        int q = wbase[warp] + __popc(b & ((1u << lane) - 1));
        int qi = cell >> 7, qj = cell & 127;
        #pragma unroll
        for (int o = 0; o < 9; ++o) {
            int ni = qi + o / 3 - 1, nj = qj + o % 3 - 1;
            int v = (ni >= 0 && ni < 128 && nj >= 0 && nj < 128) ? d_pidx[ni * 128 + nj] : -1;
            d_src[q * 12 + o] = v;
        }
        int pp = d_pidx[cell];
        d_q2p[q] = pp;
        if (pp >= 0) d_qofp[pp] = q;
    }
}

// ---------------- K6: scatter + per-q group stats + masked H --------------------
__global__ void __launch_bounds__(256) k_scatter3() {
    const int q = blockIdx.x;
    if (q >= d_qcount) return;
    const int tid = threadIdx.x;
    __shared__ int ss[12];
    __shared__ float hsm[768];
    __shared__ float gs[4][64], gq[4][64];
    if (tid < 12) ss[tid] = d_src[q * 12 + tid];
    __syncthreads();
    float a0 = 0.f, a1 = 0.f, a2 = 0.f;
    #pragma unroll
    for (int o = 0; o < 9; ++o) {
        int p = ss[o];
        if (p >= 0) {
            const float* r = d_Yt + (size_t)p * MROWS + o * 768 + tid;
            a0 += r[0]; a1 += r[256]; a2 += r[512];
        }
    }
    hsm[tid] = a0; hsm[tid + 256] = a1; hsm[tid + 512] = a2;
    if (d_q2p[q] >= 0) {
        float* h = d_H + (size_t)q * CIN + tid;
        h[0] = a0; h[256] = a1; h[512] = a2;
    }
    __syncthreads();
    const int g = tid >> 6, j = tid & 63;
    float s = 0.f, q2 = 0.f;
    #pragma unroll
    for (int t = 0; t < 3; ++t) {
        float v = hsm[g * 192 + j + t * 64];
        s += v; q2 += v * v;
    }
    gs[g][j] = s; gq[g][j] = q2;
    __syncthreads();
    #pragma unroll
    for (int st = 32; st > 0; st >>= 1) {
        if (j < st) { gs[g][j] += gs[g][j + st]; gq[g][j] += gq[g][j + st]; }
        __syncthreads();
    }
    if (j == 0) { d_gps[q * 4 + g] = gs[g][0]; d_gpq[q * 4 + g] = gq[g][0]; }
}

// ---------------- K7: reduce per-q group partials -> mu/rs ----------------------
__global__ void __launch_bounds__(256) k_grp2() {
    const int g = blockIdx.x;
    const int tid = threadIdx.x;
    __shared__ float s1[256], s2[256];
    const int qc = d_qcount;
    float s = 0.f, q2 = 0.f;
    for (int q = tid; q < qc; q += 256) {
        s += d_gps[q * 4 + g];
        q2 += d_gpq[q * 4 + g];
    }
    s1[tid] = s; s2[tid] = q2; __syncthreads();
    for (int st = 128; st > 0; st >>= 1) {
        if (tid < st) { s1[tid] += s1[tid + st]; s2[tid] += s2[tid + st]; }
        __syncthreads();
    }
    if (tid == 0) {
        float inv = 1.0f / (192.0f * 16384.0f);
        float mu = s1[0] * inv;
        float var = s2[0] * inv - mu * mu;
        d_mu[g] = mu;
        d_rs[g] = 1.0f / sqrtf(var + 1e-5f);
    }
}

// ---------------- K8: scores (contiguous H rows via qofp) ------------------------
__global__ void k_scores(const float* __restrict__ gamma, const float* __restrict__ beta,
                         const float* __restrict__ w2) {
    const int p = blockIdx.x;
    const int tid = threadIdx.x; // 128
    __shared__ float red[128];
    const int q = d_qofp[p];
    const float* hrow = d_H + (size_t)q * CIN;
    float acc = 0.f;
    #pragma unroll
    for (int it = 0; it < 6; ++it) {
        int c = it * 128 + tid;
        float x = hrow[c];
        int g = c / 192;
        float v = (x - d_mu[g]) * d_rs[g] * gamma[c] + beta[c];
        v = fmaxf(v, 0.f);
        acc += v * w2[c];
    }
    red[tid] = acc; __syncthreads();
    for (int st = 64; st > 0; st >>= 1) {
        if (tid < st) red[tid] += red[tid + st];
        __syncthreads();
    }
    if (tid == 0) d_scores[p] = red[0];
}

// ---------------- K9: argmax-greedy NMS + output ---------------------------------
__device__ __forceinline__ float read_duration(const void* p) {
    unsigned u = *(const unsigned*)p;
    float f = __int_as_float(u);
    if (f > 1e-3f && f < 1e7f) return f;
    int i = (int)u;
    if (i > 0 && i < 10000000) return (float)i;
    double d = *(const double*)p;
    if (d > 1e-3 && d < 1e7) return (float)d;
    return 30.0f;
}

__global__ void __launch_bounds__(1024) k_nms(const void* __restrict__ dur_ptr,
                                              float* __restrict__ out) {
    const int tid = threadIdx.x;
    __shared__ float ssc[PNUM];
    __shared__ float sst[PNUM], sen[PNUM];
    __shared__ unsigned char sup[PNUM];
    __shared__ float bs[1024];
    __shared__ int   bi[1024];

    float dur = read_duration(dur_ptr);
    float scale = dur / 128.0f;

    for (int i = tid; i < PNUM; i += 1024) {
        ssc[i] = d_scores[i];
        sst[i] = d_ppi[i] * scale;
        sen[i] = (d_ppj[i] + 1) * scale;
        sup[i] = 0;
    }
    __syncthreads();

    int cnt = 0;
    while (cnt < 5) {
        float best = -INFINITY; int bidx = PNUM;
        for (int i = tid; i < PNUM; i += 1024) {
            if (!sup[i]) {
                float v = ssc[i];
                if (v > best || (v == best && i < bidx)) { best = v; bidx = i; }
            }
        }
        bs[tid] = best; bi[tid] = bidx;
        __syncthreads();
        for (int st = 512; st > 0; st >>= 1) {
            if (tid < st) {
                float ov = bs[tid + st]; int oi = bi[tid + st];
                if (ov > bs[tid] || (ov == bs[tid] && oi < bi[tid])) { bs[tid] = ov; bi[tid] = oi; }
            }
            __syncthreads();
        }
        int sel = bi[0];
        if (sel >= PNUM) break;
        float si = sst[sel], ei = sen[sel];
        if (tid == 0) { out[cnt * 2] = si; out[cnt * 2 + 1] = ei; sup[sel] = 1; }
        __syncthreads();
        for (int j = tid; j < PNUM; j += 1024) {
            if (!sup[j]) {
                float inter = fminf(sen[j], ei) - fmaxf(sst[j], si);
                inter = fmaxf(inter, 0.f);
                float uni = fmaxf(sen[j], ei) - fminf(sst[j], si);
                if (inter / uni > 0.5f) sup[j] = 1;
            }
        }
        if (tid == 0) ssc[sel] = -INFINITY;
        cnt++;
        __syncthreads();
    }
    while (cnt < 5) {
        float best = -INFINITY; int bidx = PNUM;
        for (int i = tid; i < PNUM; i += 1024) {
            float v = ssc[i];
            if (v > best || (v == best && i < bidx)) { best = v; bidx = i; }
        }
        bs[tid] = best; bi[tid] = bidx;
        __syncthreads();
        for (int st = 512; st > 0; st >>= 1) {
            if (tid < st) {
                float ov = bs[tid + st]; int oi = bi[tid + st];
                if (ov > bs[tid] || (ov == bs[tid] && oi < bi[tid])) { bs[tid] = ov; bi[tid] = oi; }
            }
            __syncthreads();
        }
        int sel = bi[0];
        if (sel >= PNUM || bs[0] == -INFINITY) break;
        if (tid == 0) {
            out[cnt * 2] = sst[sel]; out[cnt * 2 + 1] = sen[sel];
            ssc[sel] = -INFINITY;
        }
        cnt++;
        __syncthreads();
    }
}

// ---------------- launch -----------------------------------------------------------
extern "C" void kernel_launch(void* const* d_in, const int* in_sizes, int n_in,
                              void* d_out, int out_size) {
    const float* fea     = (const float*)d_in[0];
    const void*  durp    = d_in[1];
    const float* conv1_w = (const float*)d_in[2];
    const float* gamma   = (const float*)d_in[3];
    const float* beta    = (const float*)d_in[4];
    const float* conv2_w = (const float*)d_in[5];
    float* out = (float*)d_out;

    k_init<<<97, 1024>>>(fea);                               // launch 0
    k_flag<<<128, 128>>>();                                  // launch 1
    k_split<<<2688, 256>>>(conv1_w);                         // launch 2
    k_gemm_mma<<<dim3(MROWS / 128, PPAD / 128), 256>>>();    // launch 3 <- ncu capture
    k_offs<<<1, 128>>>();                                    // launch 4
    k_emit<<<128, 128>>>();                                  // launch 5
    k_scatter3<<<QMAX, 256>>>();
    k_grp2<<<4, 256>>>();
    k_scores<<<PNUM, 128>>>(gamma, beta, conv2_w);
    k_nms<<<1, 1024>>>(durp, out);
}

// round 15
// speedup vs baseline: 1.3467x; 1.3467x over previous
#include <cuda_runtime.h>
#include <cuda_bf16.h>
#include <math.h>

typedef unsigned long long ull;

#define PNUM 2548      // number of masked positions (exact)
#define PPAD 2560      // padded N for GEMM
#define QMAX 16384
#define CIN  768
#define MROWS 6912     // 9 offsets * 768 cout, ordered m = o*768 + c
#define KK   2304      // 3 * 768 (hi*hi, hi*lo, lo*hi segments)
#define NCH  72        // K chunks of 32

// ---------------- scratch (static device globals; no allocation) -------------
__device__ float d_V[CIN * PPAD];
__device__ __align__(128) __nv_bfloat16 d_A2[(size_t)MROWS * KK]; // weights [m][k]
__device__ __align__(128) __nv_bfloat16 d_B2[(size_t)PPAD * KK];  // values  [p][k]
__device__ float d_Yt[(size_t)PPAD * MROWS];   // GEMM out, [p][m]
__device__ float d_H[(size_t)QMAX * CIN];      // conv1 out, masked q rows only
__device__ float d_gps[QMAX * 4];              // per-q group sums
__device__ float d_gpq[QMAX * 4];              // per-q group sumsq
__device__ int   d_pidx[QMAX];
__device__ unsigned char d_flags[QMAX];
__device__ int   d_bcnt[128];
__device__ int   d_boff[128];
__device__ int   d_src[QMAX * 12];
__device__ int   d_q2p[QMAX];
__device__ int   d_qofp[PNUM];
__device__ int   d_qcount;
__device__ int   d_ppi[PNUM];
__device__ int   d_ppj[PNUM];
__device__ float d_mu[4];
__device__ float d_rs[4];
__device__ float d_scores[PNUM];
__device__ unsigned d_done0 = 0;

// ---------------- helpers ------------------------------------------------------
__device__ __forceinline__ unsigned smem_u32(const void* p) {
    unsigned a;
    asm("{ .reg .u64 t; cvta.to.shared.u64 t, %1; cvt.u32.u64 %0, t; }" : "=r"(a) : "l"(p));
    return a;
}
__device__ __forceinline__ void cp16(unsigned dst, const void* src) {
    asm volatile("cp.async.cg.shared.global [%0], [%1], 16;" :: "r"(dst), "l"(src) : "memory");
}
__device__ __forceinline__ void cp_commit() {
    asm volatile("cp.async.commit_group;" ::: "memory");
}
__device__ __forceinline__ void cp_wait1() {
    asm volatile("cp.async.wait_group 1;" ::: "memory");
}
__device__ __forceinline__ void cp_wait0() {
    asm volatile("cp.async.wait_group 0;" ::: "memory");
}
__device__ __forceinline__ void ldmx4(unsigned addr, unsigned& r0, unsigned& r1, unsigned& r2, unsigned& r3) {
    asm volatile("ldmatrix.sync.aligned.m8n8.x4.shared.b16 {%0,%1,%2,%3}, [%4];"
                 : "=r"(r0), "=r"(r1), "=r"(r2), "=r"(r3) : "r"(addr));
}
__device__ __forceinline__ void mma16816(float* c, const unsigned* a, const unsigned* b) {
    asm volatile(
        "mma.sync.aligned.m16n8k16.row.col.f32.bf16.bf16.f32 "
        "{%0,%1,%2,%3},{%4,%5,%6,%7},{%8,%9},{%0,%1,%2,%3};"
        : "+f"(c[0]), "+f"(c[1]), "+f"(c[2]), "+f"(c[3])
        : "r"(a[0]), "r"(a[1]), "r"(a[2]), "r"(a[3]), "r"(b[0]), "r"(b[1]));
}
__device__ __forceinline__ unsigned pkbf2(float a, float b) {
    __nv_bfloat16 x = __float2bfloat16_rn(a), y = __float2bfloat16_rn(b);
    unsigned short ux = *(unsigned short*)&x, uy = *(unsigned short*)&y;
    return (unsigned)ux | ((unsigned)uy << 16);
}

// ---------------- K0: table fill (block 0) + max pool (blocks 1..96) ------------
__global__ void __launch_bounds__(1024) k_init(const float* __restrict__ fea) {
    __shared__ float xs[8][128];
    const int tid = threadIdx.x;

    if (blockIdx.x == 0) {
        for (int i = tid; i < QMAX; i += 1024) d_pidx[i] = -1;
        __syncthreads();
        if (tid < 128) { d_ppi[tid] = tid; d_ppj[tid] = tid; d_pidx[tid * 128 + tid] = tid; }
        int len = 128, pbase = 128, stride = 1, offset = 0;
        const int counts[4] = {15, 8, 8, 8};
        for (int g = 0; g < 4; ++g) {
            for (int t = 0; t < counts[g]; ++t) {
                offset += stride;
                bool k3 = (g > 0 && t == 0);
                int nl = k3 ? (len - 1) / 2 : (len - 1);
                for (int u = tid; u < nl; u += 1024) {
                    int ii = u * stride, jj = offset + u * stride, p = pbase + u;
                    d_ppi[p] = ii; d_ppj[p] = jj; d_pidx[ii * 128 + jj] = p;
                }
                pbase += nl; len = nl;
            }
            stride <<= 1;
        }
    } else {
        const int sub = tid >> 7;
        const int lt = tid & 127;
        const int c = (blockIdx.x - 1) * 8 + sub;
        float* x = xs[sub];
        x[lt] = fea[c * 128 + lt];
        d_V[c * PPAD + lt] = x[lt];
        __syncthreads();
        int len = 128, pbase = 128, stride = 1, offset = 0;
        const int counts[4] = {15, 8, 8, 8};
        for (int g = 0; g < 4; ++g) {
            for (int t = 0; t < counts[g]; ++t) {
                offset += stride;
                bool k3 = (g > 0 && t == 0);
                int nl = k3 ? (len - 1) / 2 : (len - 1);
                float v = 0.f;
                if (lt < nl)
                    v = k3 ? fmaxf(fmaxf(x[2 * lt], x[2 * lt + 1]), x[2 * lt + 2])
                           : fmaxf(x[lt], x[lt + 1]);
                __syncthreads();
                if (lt < nl) { x[lt] = v; d_V[c * PPAD + pbase + lt] = v; }
                __syncthreads();
                pbase += nl; len = nl;
            }
            stride <<= 1;
        }
    }
}

// ---------------- K1: dilation flags + counts + (last block) prefix scan ---------
__global__ void __launch_bounds__(128) k_flago() {
    const int tid = threadIdx.x;
    const int cell = blockIdx.x * 128 + tid;
    const int qi = cell >> 7, qj = cell & 127;
    bool f = false;
    #pragma unroll
    for (int o = 0; o < 9; ++o) {
        int ni = qi + o / 3 - 1, nj = qj + o % 3 - 1;
        if (ni >= 0 && ni < 128 && nj >= 0 && nj < 128 && d_pidx[ni * 128 + nj] >= 0) f = true;
    }
    d_flags[cell] = f ? 1 : 0;
    unsigned b = __ballot_sync(0xffffffff, f);
    __shared__ int wc[4];
    if ((tid & 31) == 0) wc[tid >> 5] = __popc(b);
    __syncthreads();
    if (tid == 0) d_bcnt[blockIdx.x] = wc[0] + wc[1] + wc[2] + wc[3];

    __threadfence();
    __syncthreads();
    __shared__ int last;
    if (tid == 0) {
        unsigned old = atomicAdd(&d_done0, 1);
        last = (old == gridDim.x - 1);
        if (last) d_done0 = 0;
    }
    __syncthreads();
    if (last) {
        __shared__ int s[128];
        s[tid] = d_bcnt[tid];
        __syncthreads();
        int v = s[tid];
        for (int off = 1; off < 128; off <<= 1) {
            int u = (tid >= off) ? s[tid - off] : 0;
            __syncthreads();
            s[tid] += u;
            __syncthreads();
        }
        d_boff[tid] = s[tid] - v;   // exclusive
        if (tid == 127) d_qcount = s[127];
    }
}

// ---------------- K2: merged A' build + B' build + q-table emit -------------------
// blocks [0,768): weight split; [768,2688): value transpose+split; [2688,2816): emit
__global__ void __launch_bounds__(256) k_split(const float* __restrict__ w) {
    const int tid = threadIdx.x;
    if (blockIdx.x < 768) {
        const int cout = blockIdx.x;
        __shared__ float ws[CIN * 9];
        for (int i = tid; i < CIN * 9; i += 256) ws[i] = w[(size_t)cout * CIN * 9 + i];
        __syncthreads();
        #pragma unroll
        for (int o = 0; o < 9; ++o) {
            size_t mrow = (size_t)(o * 768 + cout) * KK;
            for (int k2 = tid; k2 < 384; k2 += 256) {
                int k = k2 * 2;
                float x0 = ws[k * 9 + o], x1 = ws[(k + 1) * 9 + o];
                float h0f = __bfloat162float(__float2bfloat16_rn(x0));
                float h1f = __bfloat162float(__float2bfloat16_rn(x1));
                unsigned hi = pkbf2(x0, x1);
                unsigned lo = pkbf2(x0 - h0f, x1 - h1f);
                *(unsigned*)&d_A2[mrow + k]        = hi;
                *(unsigned*)&d_A2[mrow + 768 + k]  = hi;
                *(unsigned*)&d_A2[mrow + 1536 + k] = lo;
            }
        }
    } else if (blockIdx.x < 2688) {
        __shared__ float tile[32][33];
        const int b = blockIdx.x - 768;        // 0..1919
        const int p0 = (b % 80) * 32;
        const int c0 = (b / 80) * 32;
        const int tx = tid & 31, ty = tid >> 5; // (32,8)
        #pragma unroll
        for (int i = ty; i < 32; i += 8)
            tile[i][tx] = (p0 + tx < PNUM) ? d_V[(size_t)(c0 + i) * PPAD + p0 + tx] : 0.f;
        __syncthreads();
        #pragma unroll
        for (int i = ty; i < 32; i += 8) {
            if (tx < 16) {
                int p = p0 + i;
                int k = c0 + tx * 2;
                float x0 = tile[tx * 2][i], x1 = tile[tx * 2 + 1][i];
                float h0f = __bfloat162float(__float2bfloat16_rn(x0));
                float h1f = __bfloat162float(__float2bfloat16_rn(x1));
                unsigned hi = pkbf2(x0, x1);
                unsigned lo = pkbf2(x0 - h0f, x1 - h1f);
                size_t prow = (size_t)p * KK;
                *(unsigned*)&d_B2[prow + k]        = hi;
                *(unsigned*)&d_B2[prow + 768 + k]  = lo;
                *(unsigned*)&d_B2[prow + 1536 + k] = hi;
            }
        }
    } else {
        const int row = blockIdx.x - 2688;     // 0..127
        const int lane = tid & 31, warp = tid >> 5;
        bool f = false;
        int cell = 0;
        if (tid < 128) {
            cell = row * 128 + tid;
            f = d_flags[cell] != 0;
        }
        unsigned b = __ballot_sync(0xffffffff, f);
        __shared__ int wbase[8];
        if (lane == 0) wbase[warp] = __popc(b);
        __syncthreads();
        if (tid == 0) {
            int acc = d_boff[row];
            #pragma unroll
            for (int wdx = 0; wdx < 4; ++wdx) { int t = wbase[wdx]; wbase[wdx] = acc; acc += t; }
        }
        __syncthreads();
        if (f) {
            int q = wbase[warp] + __popc(b & ((1u << lane) - 1));
            int qi = cell >> 7, qj = cell & 127;
            #pragma unroll
            for (int o = 0; o < 9; ++o) {
                int ni = qi + o / 3 - 1, nj = qj + o % 3 - 1;
                int v = (ni >= 0 && ni < 128 && nj >= 0 && nj < 128) ? d_pidx[ni * 128 + nj] : -1;
                d_src[q * 12 + o] = v;
            }
            int pp = d_pidx[cell];
            d_q2p[q] = pp;
            if (pp >= 0) d_qofp[pp] = q;
        }
    }
}

// ---------------- K3: bf16 mma.sync GEMM  Yt[2560 x 6912] = B2 @ A2^T -----------
// CTA 128x128, 4 warps (2m x 2n), warp tile 64x64, K-chunks of 32, 3-stage cp.async.
__global__ void __launch_bounds__(128, 2) k_gemm_mma() {
    __shared__ __align__(16) uint4 smbuf[3][1024];   // per stage: A 8KB | B 8KB
    const int tid = threadIdx.x;
    const int wid = tid >> 5;
    const int lane = tid & 31;
    const int wm = wid >> 1;
    const int wn = wid & 1;
    const int bn0 = blockIdx.x * 128;   // over MROWS
    const int bm0 = blockIdx.y * 128;   // over PPAD

    const unsigned smb = smem_u32(&smbuf[0][0]);

    const __nv_bfloat16* Ag = d_B2 + (size_t)bm0 * KK;
    const __nv_bfloat16* Bg = d_A2 + (size_t)bn0 * KK;

    auto issue = [&](int kc, int buf) {
        unsigned base = smb + buf * 16384;
        #pragma unroll
        for (int j = 0; j < 8; ++j) {
            int cid = tid + j * 128;
            int half = cid >> 9;
            int lc = cid & 511;
            int r = lc >> 2, c = lc & 3;
            unsigned dst = base + half * 8192 + (unsigned)(r * 64 + ((c ^ ((r >> 1) & 3)) << 4));
            const __nv_bfloat16* src = (half ? Bg : Ag) + (size_t)r * KK + kc * 32 + c * 8;
            cp16(dst, src);
        }
        cp_commit();
    };

    float acc[4][8][4];
    #pragma unroll
    for (int i = 0; i < 4; i++)
        #pragma unroll
        for (int j = 0; j < 8; j++)
            #pragma unroll
            for (int v = 0; v < 4; v++) acc[i][j][v] = 0.f;

    issue(0, 0);
    issue(1, 1);

    const int l15 = lane & 15, hl = lane >> 4;
    const int rowA = wm * 64 + l15;
    const int sA = (rowA >> 1) & 3;
    const int rowBb = wn * 64;

    for (int kt = 0; kt < NCH; ++kt) {
        if (kt < NCH - 1) cp_wait1(); else cp_wait0();
        __syncthreads();
        if (kt + 2 < NCH) issue(kt + 2, (kt + 2) % 3);

        unsigned Asm = smb + (kt % 3) * 16384;
        unsigned Bsm = Asm + 8192;

        #pragma unroll
        for (int kg = 0; kg < 2; ++kg) {
            unsigned af[4][4], bf[8][2];
            #pragma unroll
            for (int mt = 0; mt < 4; ++mt) {
                unsigned addr = Asm + (unsigned)((rowA + mt * 16) * 64 + (((kg * 2 + hl) ^ sA) << 4));
                ldmx4(addr, af[mt][0], af[mt][1], af[mt][2], af[mt][3]);
            }
            #pragma unroll
            for (int u = 0; u < 4; ++u) {
                int row = rowBb + u * 16 + l15;
                int sB = (row >> 1) & 3;
                unsigned addr = Bsm + (unsigned)(row * 64 + (((kg * 2 + hl) ^ sB) << 4));
                unsigned r0, r1, r2, r3;
                ldmx4(addr, r0, r1, r2, r3);
                bf[2 * u][0] = r0; bf[2 * u + 1][0] = r1;
                bf[2 * u][1] = r2; bf[2 * u + 1][1] = r3;
            }
            #pragma unroll
            for (int mt = 0; mt < 4; ++mt)
                #pragma unroll
                for (int nt = 0; nt < 8; ++nt)
                    mma16816(acc[mt][nt], af[mt], bf[nt]);
        }
        __syncthreads();
    }

    const int r0 = lane >> 2, c0 = (lane & 3) * 2;
    #pragma unroll
    for (int mt = 0; mt < 4; ++mt) {
        int m = bm0 + wm * 64 + mt * 16 + r0;
        float* y0 = d_Yt + (size_t)m * MROWS + bn0 + wn * 64;
        float* y1 = y0 + (size_t)8 * MROWS;
        #pragma unroll
        for (int nt = 0; nt < 8; ++nt) {
            *(float2*)(y0 + nt * 8 + c0) = make_float2(acc[mt][nt][0], acc[mt][nt][1]);
            *(float2*)(y1 + nt * 8 + c0) = make_float2(acc[mt][nt][2], acc[mt][nt][3]);
        }
    }
}

// ---------------- K4: scatter (float4, 192 threads) + per-q group stats ----------
__global__ void __launch_bounds__(192) k_scatter5() {
    const int q = blockIdx.x;
    if (q >= d_qcount) return;
    const int tid = threadIdx.x;   // 0..191, covers channels [tid*4, tid*4+4)
    __shared__ int ss[12];
    __shared__ float gs[4][64], gq[4][64];
    if (tid < 12) ss[tid] = d_src[q * 12 + tid];
    __syncthreads();
    float4 a = make_float4(0.f, 0.f, 0.f, 0.f);
    #pragma unroll
    for (int o = 0; o < 9; ++o) {
        int p = ss[o];
        if (p >= 0) {
            float4 v = *((const float4*)(d_Yt + (size_t)p * MROWS + o * 768) + tid);
            a.x += v.x; a.y += v.y; a.z += v.z; a.w += v.w;
        }
    }
    if (d_q2p[q] >= 0)
        *((float4*)(d_H + (size_t)q * CIN) + tid) = a;

    // group stats: group g = tid/48 (192 channels per group / 4 per thread)
    const int g = tid / 48, j = tid % 48;
    float s = a.x + a.y + a.z + a.w;
    float q2 = a.x * a.x + a.y * a.y + a.z * a.z + a.w * a.w;
    // zero-pad to 64-lane tree
    if (j == 0) {
        #pragma unroll
        for (int t = 48; t < 64; ++t) { gs[g][t] = 0.f; gq[g][t] = 0.f; }
    }
    __syncthreads();
    gs[g][j] = s; gq[g][j] = q2;
    __syncthreads();
    #pragma unroll
    for (int st = 32; st > 0; st >>= 1) {
        if (j < st) { gs[g][j] += gs[g][j + st]; gq[g][j] += gq[g][j + st]; }
        __syncthreads();
    }
    if (j == 0) { d_gps[q * 4 + g] = gs[g][0]; d_gpq[q * 4 + g] = gq[g][0]; }
}

// ---------------- K5: reduce per-q group partials -> mu/rs ----------------------
__global__ void __launch_bounds__(256) k_grp2() {
    const int g = blockIdx.x;
    const int tid = threadIdx.x;
    __shared__ float s1[256], s2[256];
    const int qc = d_qcount;
    float s = 0.f, q2 = 0.f;
    for (int q = tid; q < qc; q += 256) {
        s += d_gps[q * 4 + g];
        q2 += d_gpq[q * 4 + g];
    }
    s1[tid] = s; s2[tid] = q2; __syncthreads();
    for (int st = 128; st > 0; st >>= 1) {
        if (tid < st) { s1[tid] += s1[tid + st]; s2[tid] += s2[tid + st]; }
        __syncthreads();
    }
    if (tid == 0) {
        float inv = 1.0f / (192.0f * 16384.0f);
        float mu = s1[0] * inv;
        float var = s2[0] * inv - mu * mu;
        d_mu[g] = mu;
        d_rs[g] = 1.0f / sqrtf(var + 1e-5f);
    }
}

// ---------------- K6: scores (contiguous H rows via qofp) ------------------------
__global__ void k_scores(const float* __restrict__ gamma, const float* __restrict__ beta,
                         const float* __restrict__ w2) {
    const int p = blockIdx.x;
    const int tid = threadIdx.x; // 128
    __shared__ float red[128];
    const int q = d_qofp[p];
    const float* hrow = d_H + (size_t)q * CIN;
    float acc = 0.f;
    #pragma unroll
    for (int it = 0; it < 6; ++it) {
        int c = it * 128 + tid;
        float x = hrow[c];
        int g = c / 192;
        float v = (x - d_mu[g]) * d_rs[g] * gamma[c] + beta[c];
        v = fmaxf(v, 0.f);
        acc += v * w2[c];
    }
    red[tid] = acc; __syncthreads();
    for (int st = 64; st > 0; st >>= 1) {
        if (tid < st) red[tid] += red[tid + st];
        __syncthreads();
    }
    if (tid == 0) d_scores[p] = red[0];
}

// ---------------- K7: argmax-greedy NMS + output ---------------------------------
__device__ __forceinline__ float read_duration(const void* p) {
    unsigned u = *(const unsigned*)p;
    float f = __int_as_float(u);
    if (f > 1e-3f && f < 1e7f) return f;
    int i = (int)u;
    if (i > 0 && i < 10000000) return (float)i;
    double d = *(const double*)p;
    if (d > 1e-3 && d < 1e7) return (float)d;
    return 30.0f;
}

__global__ void __launch_bounds__(1024) k_nms(const void* __restrict__ dur_ptr,
                                              float* __restrict__ out) {
    const int tid = threadIdx.x;
    __shared__ float ssc[PNUM];
    __shared__ float sst[PNUM], sen[PNUM];
    __shared__ unsigned char sup[PNUM];
    __shared__ float bs[1024];
    __shared__ int   bi[1024];

    float dur = read_duration(dur_ptr);
    float scale = dur / 128.0f;

    for (int i = tid; i < PNUM; i += 1024) {
        ssc[i] = d_scores[i];
        sst[i] = d_ppi[i] * scale;
        sen[i] = (d_ppj[i] + 1) * scale;
        sup[i] = 0;
    }
    __syncthreads();

    int cnt = 0;
    while (cnt < 5) {
        float best = -INFINITY; int bidx = PNUM;
        for (int i = tid; i < PNUM; i += 1024) {
            if (!sup[i]) {
                float v = ssc[i];
                if (v > best || (v == best && i < bidx)) { best = v; bidx = i; }
            }
        }
        bs[tid] = best; bi[tid] = bidx;
        __syncthreads();
        for (int st = 512; st > 0; st >>= 1) {
            if (tid < st) {
                float ov = bs[tid + st]; int oi = bi[tid + st];
                if (ov > bs[tid] || (ov == bs[tid] && oi < bi[tid])) { bs[tid] = ov; bi[tid] = oi; }
            }
            __syncthreads();
        }
        int sel = bi[0];
        if (sel >= PNUM) break;
        float si = sst[sel], ei = sen[sel];
        if (tid == 0) { out[cnt * 2] = si; out[cnt * 2 + 1] = ei; sup[sel] = 1; }
        __syncthreads();
        for (int j = tid; j < PNUM; j += 1024) {
            if (!sup[j]) {
                float inter = fminf(sen[j], ei) - fmaxf(sst[j], si);
                inter = fmaxf(inter, 0.f);
                float uni = fmaxf(sen[j], ei) - fminf(sst[j], si);
                if (inter / uni > 0.5f) sup[j] = 1;
            }
        }
        if (tid == 0) ssc[sel] = -INFINITY;
        cnt++;
        __syncthreads();
    }
    while (cnt < 5) {
        float best = -INFINITY; int bidx = PNUM;
        for (int i = tid; i < PNUM; i += 1024) {
            float v = ssc[i];
            if (v > best || (v == best && i < bidx)) { best = v; bidx = i; }
        }
        bs[tid] = best; bi[tid] = bidx;
        __syncthreads();
        for (int st = 512; st > 0; st >>= 1) {
            if (tid < st) {
                float ov = bs[tid + st]; int oi = bi[tid + st];
                if (ov > bs[tid] || (ov == bs[tid] && oi < bi[tid])) { bs[tid] = ov; bi[tid] = oi; }
            }
            __syncthreads();
        }
        int sel = bi[0];
        if (sel >= PNUM || bs[0] == -INFINITY) break;
        if (tid == 0) {
            out[cnt * 2] = sst[sel]; out[cnt * 2 + 1] = sen[sel];
            ssc[sel] = -INFINITY;
        }
        cnt++;
        __syncthreads();
    }
}

// ---------------- launch -----------------------------------------------------------
extern "C" void kernel_launch(void* const* d_in, const int* in_sizes, int n_in,
                              void* d_out, int out_size) {
    const float* fea     = (const float*)d_in[0];
    const void*  durp    = d_in[1];
    const float* conv1_w = (const float*)d_in[2];
    const float* gamma   = (const float*)d_in[3];
    const float* beta    = (const float*)d_in[4];
    const float* conv2_w = (const float*)d_in[5];
    float* out = (float*)d_out;

    k_init<<<97, 1024>>>(fea);                               // launch 0
    k_flago<<<128, 128>>>();                                 // launch 1
    k_split<<<2816, 256>>>(conv1_w);                         // launch 2 (incl. emit)
    k_gemm_mma<<<dim3(MROWS / 128, PPAD / 128), 128>>>();    // launch 3 <- ncu capture
    k_scatter5<<<QMAX, 192>>>();                             // launch 4
    k_grp2<<<4, 256>>>();                                    // launch 5
    k_scores<<<PNUM, 128>>>(gamma, beta, conv2_w);           // launch 6
    k_nms<<<1, 1024>>>(durp, out);                           // launch 7
}